// round 3
// baseline (speedup 1.0000x reference)
#include <cuda_runtime.h>
#include <cuda_bf16.h>
#include <math.h>

// Problem constants
#define B_  2
#define T_  2048
#define D_  4096
#define H_  32
#define KVH_ 8
#define HD_ 128
#define NREP_ 4
#define BT_ (B_ * T_)            // 4096

// Scratch (allocation-free: __device__ globals)
__device__ float g_q[(size_t)BT_ * H_ * HD_];     // [B,T,H,HD]
__device__ float g_k[(size_t)BT_ * KVH_ * HD_];   // [B,T,KVH,HD]
__device__ float g_v[(size_t)BT_ * KVH_ * HD_];
__device__ float g_ctx[(size_t)BT_ * H_ * HD_];   // [B,T,H*HD]

// ---------------------------------------------------------------------------
// SGEMM NT: C[M,N] = A[M,K] * B[N,K]^T   (A,B,C row-major fp32)
// 128x128 tile, BK=16, 256 threads, 8x8 per-thread accumulators.
// Software-pipelined global loads (prefetch next slice into registers).
// M,N multiples of 128; K multiple of 16.
// ---------------------------------------------------------------------------
__global__ __launch_bounds__(256) void sgemm_nt(
    const float* __restrict__ A, const float* __restrict__ Bm,
    float* __restrict__ C, int M, int N, int K)
{
    __shared__ float As[16][132];
    __shared__ float Bs[16][132];

    const int tid = threadIdx.x;
    const int tx = tid & 15;
    const int ty = tid >> 4;
    const int m0 = blockIdx.y * 128;
    const int n0 = blockIdx.x * 128;

    const float* Aptr = A + (size_t)m0 * K;
    const float* Bptr = Bm + (size_t)n0 * K;

    // each thread loads 2 float4 from A and 2 from B per K-slice
    int row0 = (tid) >> 2;                 // 0..63   (idx = tid)
    int c40  = (tid) & 3;
    int row1 = (tid + 256) >> 2;           // 64..127 (idx = tid+256)
    int c41  = (tid + 256) & 3;

    float acc[8][8];
#pragma unroll
    for (int i = 0; i < 8; i++)
#pragma unroll
        for (int j = 0; j < 8; j++) acc[i][j] = 0.f;

    // prologue: load slice 0 into registers
    float4 ra0 = *(const float4*)(Aptr + (size_t)row0 * K + c40 * 4);
    float4 ra1 = *(const float4*)(Aptr + (size_t)row1 * K + c41 * 4);
    float4 rb0 = *(const float4*)(Bptr + (size_t)row0 * K + c40 * 4);
    float4 rb1 = *(const float4*)(Bptr + (size_t)row1 * K + c41 * 4);

    for (int k0 = 0; k0 < K; k0 += 16) {
        // store staged registers to smem
        As[c40 * 4 + 0][row0] = ra0.x; As[c40 * 4 + 1][row0] = ra0.y;
        As[c40 * 4 + 2][row0] = ra0.z; As[c40 * 4 + 3][row0] = ra0.w;
        As[c41 * 4 + 0][row1] = ra1.x; As[c41 * 4 + 1][row1] = ra1.y;
        As[c41 * 4 + 2][row1] = ra1.z; As[c41 * 4 + 3][row1] = ra1.w;
        Bs[c40 * 4 + 0][row0] = rb0.x; Bs[c40 * 4 + 1][row0] = rb0.y;
        Bs[c40 * 4 + 2][row0] = rb0.z; Bs[c40 * 4 + 3][row0] = rb0.w;
        Bs[c41 * 4 + 0][row1] = rb1.x; Bs[c41 * 4 + 1][row1] = rb1.y;
        Bs[c41 * 4 + 2][row1] = rb1.z; Bs[c41 * 4 + 3][row1] = rb1.w;
        __syncthreads();

        // prefetch next slice while computing this one
        int kn = k0 + 16;
        if (kn < K) {
            ra0 = *(const float4*)(Aptr + (size_t)row0 * K + kn + c40 * 4);
            ra1 = *(const float4*)(Aptr + (size_t)row1 * K + kn + c41 * 4);
            rb0 = *(const float4*)(Bptr + (size_t)row0 * K + kn + c40 * 4);
            rb1 = *(const float4*)(Bptr + (size_t)row1 * K + kn + c41 * 4);
        }

#pragma unroll
        for (int k = 0; k < 16; k++) {
            float4 a0 = *(const float4*)&As[k][ty * 8];
            float4 a1 = *(const float4*)&As[k][ty * 8 + 4];
            float4 b0 = *(const float4*)&Bs[k][tx * 8];
            float4 b1 = *(const float4*)&Bs[k][tx * 8 + 4];
            float a[8] = {a0.x, a0.y, a0.z, a0.w, a1.x, a1.y, a1.z, a1.w};
            float b[8] = {b0.x, b0.y, b0.z, b0.w, b1.x, b1.y, b1.z, b1.w};
#pragma unroll
            for (int i = 0; i < 8; i++)
#pragma unroll
                for (int j = 0; j < 8; j++) acc[i][j] = fmaf(a[i], b[j], acc[i][j]);
        }
        __syncthreads();
    }

#pragma unroll
    for (int i = 0; i < 8; i++) {
        float* crow = C + (size_t)(m0 + ty * 8 + i) * N + n0 + tx * 8;
        float4 v0 = make_float4(acc[i][0], acc[i][1], acc[i][2], acc[i][3]);
        float4 v1 = make_float4(acc[i][4], acc[i][5], acc[i][6], acc[i][7]);
        *(float4*)crow = v0;
        *(float4*)(crow + 4) = v1;
    }
}

// ---------------------------------------------------------------------------
// RoPE: interleaved pair rotation. t laid out [B,T,NH,HD]; freqs [T, HD/2].
// One thread per (b,t,h,pair).
// ---------------------------------------------------------------------------
__global__ void rope_kernel(float* __restrict__ tns,
                            const float* __restrict__ fcos,
                            const float* __restrict__ fsin,
                            int NH, int total)   // total = B*T*NH*(HD/2)
{
    int i = blockIdx.x * blockDim.x + threadIdx.x;
    if (i >= total) return;
    int p = i & 63;                  // HD/2 = 64
    int rem = i >> 6;                // b*T*NH + t*NH + h
    int bt = rem / NH;
    int t = bt & (T_ - 1);
    float c = fcos[t * 64 + p];
    float s = fsin[t * 64 + p];
    float2 v = *(float2*)(tns + (size_t)i * 2);
    float2 r;
    r.x = v.x * c - v.y * s;
    r.y = v.x * s + v.y * c;
    *(float2*)(tns + (size_t)i * 2) = r;
}

// ---------------------------------------------------------------------------
// Flash attention (non-causal). Grid: (T/64, B*H). 256 threads.
// Q tile 64x128 in smem; loop 64-key tiles; online softmax.
// Thread grid 16x16: S block 4x4 per thread, O block 4 rows x 8 cols.
// ---------------------------------------------------------------------------
#define FL_SMEM_FLOATS (3 * 64 * 132 + 64 * 68 + 128)
#define FL_SMEM_BYTES  (FL_SMEM_FLOATS * 4)

__global__ __launch_bounds__(256) void flash_kernel(
    const float* __restrict__ Q, const float* __restrict__ Kg,
    const float* __restrict__ Vg, float* __restrict__ Og)
{
    extern __shared__ float sm[];
    float* Qs = sm;                    // 64 x 132
    float* Ks = Qs + 64 * 132;
    float* Vs = Ks + 64 * 132;
    float* Ps = Vs + 64 * 132;         // 64 x 68
    float* row_m = Ps + 64 * 68;       // 64
    float* row_l = row_m + 64;         // 64

    const int tid = threadIdx.x;
    const int tx = tid & 15;
    const int ty = tid >> 4;
    const int q0 = blockIdx.x * 64;
    const int bh = blockIdx.y;
    const int b = bh >> 5;             // /H_
    const int h = bh & 31;
    const int kvh = h >> 2;            // /NREP_

    const float scale = 0.08838834764831845f;   // 1/sqrt(128)

    const float* Qbase = Q + (((size_t)b * T_) * H_ + h) * HD_;
    const float* Kbase = Kg + (((size_t)b * T_) * KVH_ + kvh) * HD_;
    const float* Vbase = Vg + (((size_t)b * T_) * KVH_ + kvh) * HD_;

    // load Q tile: 64 rows x 128 cols (row stride H_*HD_ = 4096 floats)
    for (int idx = tid; idx < 64 * 32; idx += 256) {
        int row = idx >> 5;
        int c4 = idx & 31;
        float4 v = *(const float4*)(Qbase + (size_t)(q0 + row) * (H_ * HD_) + c4 * 4);
        *(float4*)&Qs[row * 132 + c4 * 4] = v;
    }
    if (tid < 64) { row_m[tid] = -1e30f; row_l[tid] = 0.f; }

    float o_acc[4][8];
#pragma unroll
    for (int i = 0; i < 4; i++)
#pragma unroll
        for (int j = 0; j < 8; j++) o_acc[i][j] = 0.f;

    for (int kt = 0; kt < T_ / 64; kt++) {
        // load K/V tiles (row stride KVH_*HD_ = 1024 floats)
        for (int idx = tid; idx < 64 * 32; idx += 256) {
            int row = idx >> 5;
            int c4 = idx & 31;
            size_t off = (size_t)(kt * 64 + row) * (KVH_ * HD_) + c4 * 4;
            *(float4*)&Ks[row * 132 + c4 * 4] = *(const float4*)(Kbase + off);
            *(float4*)&Vs[row * 132 + c4 * 4] = *(const float4*)(Vbase + off);
        }
        __syncthreads();

        // S = scale * Q * K^T  (4x4 per thread)
        float sv[4][4];
#pragma unroll
        for (int i = 0; i < 4; i++)
#pragma unroll
            for (int j = 0; j < 4; j++) sv[i][j] = 0.f;

#pragma unroll 4
        for (int c4 = 0; c4 < 32; c4++) {
            float4 a[4], bb[4];
#pragma unroll
            for (int i = 0; i < 4; i++)
                a[i] = *(const float4*)&Qs[(ty * 4 + i) * 132 + c4 * 4];
#pragma unroll
            for (int j = 0; j < 4; j++)
                bb[j] = *(const float4*)&Ks[(tx * 4 + j) * 132 + c4 * 4];
#pragma unroll
            for (int i = 0; i < 4; i++)
#pragma unroll
                for (int j = 0; j < 4; j++) {
                    sv[i][j] = fmaf(a[i].x, bb[j].x, sv[i][j]);
                    sv[i][j] = fmaf(a[i].y, bb[j].y, sv[i][j]);
                    sv[i][j] = fmaf(a[i].z, bb[j].z, sv[i][j]);
                    sv[i][j] = fmaf(a[i].w, bb[j].w, sv[i][j]);
                }
        }

        // online softmax per row (rows ty*4+i owned by the 16-lane tx group)
        float alpha[4];
#pragma unroll
        for (int i = 0; i < 4; i++) {
            int row = ty * 4 + i;
            float mx = -1e30f;
#pragma unroll
            for (int j = 0; j < 4; j++) {
                sv[i][j] *= scale;
                mx = fmaxf(mx, sv[i][j]);
            }
#pragma unroll
            for (int off = 8; off >= 1; off >>= 1)
                mx = fmaxf(mx, __shfl_xor_sync(0xffffffffu, mx, off, 16));
            float m_old = row_m[row];
            float m_new = fmaxf(m_old, mx);
            alpha[i] = __expf(m_old - m_new);
            float ls = 0.f;
#pragma unroll
            for (int j = 0; j < 4; j++) {
                sv[i][j] = __expf(sv[i][j] - m_new);
                ls += sv[i][j];
            }
#pragma unroll
            for (int off = 8; off >= 1; off >>= 1)
                ls += __shfl_xor_sync(0xffffffffu, ls, off, 16);
            float l_new = row_l[row] * alpha[i] + ls;
            if (tx == 0) { row_m[row] = m_new; row_l[row] = l_new; }
            // rescale O accumulator
#pragma unroll
            for (int j = 0; j < 8; j++) o_acc[i][j] *= alpha[i];
            // stage P
#pragma unroll
            for (int j = 0; j < 4; j++)
                Ps[row * 68 + tx * 4 + j] = sv[i][j];
        }
        __syncthreads();

        // O += P * V   (rows ty*4+i, cols tx*8 .. tx*8+7)
#pragma unroll 8
        for (int s = 0; s < 64; s++) {
            float4 v0 = *(const float4*)&Vs[s * 132 + tx * 8];
            float4 v1 = *(const float4*)&Vs[s * 132 + tx * 8 + 4];
#pragma unroll
            for (int i = 0; i < 4; i++) {
                float p = Ps[(ty * 4 + i) * 68 + s];
                o_acc[i][0] = fmaf(p, v0.x, o_acc[i][0]);
                o_acc[i][1] = fmaf(p, v0.y, o_acc[i][1]);
                o_acc[i][2] = fmaf(p, v0.z, o_acc[i][2]);
                o_acc[i][3] = fmaf(p, v0.w, o_acc[i][3]);
                o_acc[i][4] = fmaf(p, v1.x, o_acc[i][4]);
                o_acc[i][5] = fmaf(p, v1.y, o_acc[i][5]);
                o_acc[i][6] = fmaf(p, v1.z, o_acc[i][6]);
                o_acc[i][7] = fmaf(p, v1.w, o_acc[i][7]);
            }
        }
        __syncthreads();
    }

    // normalize and write ctx [B,T,H*HD]
#pragma unroll
    for (int i = 0; i < 4; i++) {
        int row = ty * 4 + i;
        float inv = 1.0f / row_l[row];
        float* op = Og + (((size_t)b * T_ + q0 + row) * H_ + h) * HD_ + tx * 8;
        float4 v0 = make_float4(o_acc[i][0] * inv, o_acc[i][1] * inv,
                                o_acc[i][2] * inv, o_acc[i][3] * inv);
        float4 v1 = make_float4(o_acc[i][4] * inv, o_acc[i][5] * inv,
                                o_acc[i][6] * inv, o_acc[i][7] * inv);
        *(float4*)op = v0;
        *(float4*)(op + 4) = v1;
    }
}

// ---------------------------------------------------------------------------
// kernel_launch
// Inputs: 0:x 1:wq 2:wk 3:wv 4:wo 5:freqs_cos 6:freqs_sin 7:start_pos
// ---------------------------------------------------------------------------
extern "C" void kernel_launch(void* const* d_in, const int* in_sizes, int n_in,
                              void* d_out, int out_size)
{
    const float* x  = (const float*)d_in[0];
    const float* wq = (const float*)d_in[1];
    const float* wk = (const float*)d_in[2];
    const float* wv = (const float*)d_in[3];
    const float* wo = (const float*)d_in[4];
    const float* fc = (const float*)d_in[5];
    const float* fs = (const float*)d_in[6];
    float* out = (float*)d_out;

    float *q, *k, *v, *ctx;
    cudaGetSymbolAddress((void**)&q,   g_q);
    cudaGetSymbolAddress((void**)&k,   g_k);
    cudaGetSymbolAddress((void**)&v,   g_v);
    cudaGetSymbolAddress((void**)&ctx, g_ctx);

    // QKV projections
    {
        dim3 gq(D_ / 128, BT_ / 128);
        sgemm_nt<<<gq, 256>>>(x, wq, q, BT_, D_, D_);
        dim3 gkv((KVH_ * HD_) / 128, BT_ / 128);
        sgemm_nt<<<gkv, 256>>>(x, wk, k, BT_, KVH_ * HD_, D_);
        sgemm_nt<<<gkv, 256>>>(x, wv, v, BT_, KVH_ * HD_, D_);
    }

    // RoPE
    {
        int totq = BT_ * H_ * (HD_ / 2);
        rope_kernel<<<(totq + 255) / 256, 256>>>(q, fc, fs, H_, totq);
        int totk = BT_ * KVH_ * (HD_ / 2);
        rope_kernel<<<(totk + 255) / 256, 256>>>(k, fc, fs, KVH_, totk);
    }

    // Flash attention
    {
        cudaFuncSetAttribute(flash_kernel,
                             cudaFuncAttributeMaxDynamicSharedMemorySize,
                             FL_SMEM_BYTES);
        dim3 g(T_ / 64, B_ * H_);
        flash_kernel<<<g, 256, FL_SMEM_BYTES>>>(q, k, v, ctx);
    }

    // Output projection
    {
        dim3 go(D_ / 128, BT_ / 128);
        sgemm_nt<<<go, 256>>>(ctx, wo, out, BT_, D_, D_);
    }
}

// round 4
// speedup vs baseline: 3.8742x; 3.8742x over previous
#include <cuda_runtime.h>
#include <cuda_bf16.h>
#include <cstdint>
#include <math.h>

// Problem constants
#define B_  2
#define T_  2048
#define D_  4096
#define H_  32
#define KVH_ 8
#define HD_ 128
#define BT_ (B_ * T_)            // 4096

// Scratch (allocation-free: __device__ globals)
__device__ float g_q[(size_t)BT_ * H_ * HD_];     // [B,T,H,HD]
__device__ float g_k[(size_t)BT_ * KVH_ * HD_];   // [B,T,KVH,HD]
__device__ float g_v[(size_t)BT_ * KVH_ * HD_];
__device__ float g_ctx[(size_t)BT_ * H_ * HD_];   // [B,T,H*HD]

// ---------------------------------------------------------------------------
// tf32 helpers
// ---------------------------------------------------------------------------
__device__ __forceinline__ uint32_t f2tf(float f) {
    uint32_t u;
    asm("cvt.rna.tf32.f32 %0, %1;" : "=r"(u) : "f"(f));
    return u;
}
__device__ __forceinline__ float ex2f(float x) {
    float y;
    asm("ex2.approx.ftz.f32 %0, %1;" : "=f"(y) : "f"(x));
    return y;
}
// D = A(16x8) * B(8x8) + C, tf32 inputs, f32 accum.
__device__ __forceinline__ void mma_tf32(float* d, const uint32_t* a,
                                         const uint32_t* b, const float* c) {
    asm volatile(
        "mma.sync.aligned.m16n8k8.row.col.f32.tf32.tf32.f32 "
        "{%0,%1,%2,%3}, {%4,%5,%6,%7}, {%8,%9}, {%10,%11,%12,%13};"
        : "=f"(d[0]), "=f"(d[1]), "=f"(d[2]), "=f"(d[3])
        : "r"(a[0]), "r"(a[1]), "r"(a[2]), "r"(a[3]),
          "r"(b[0]), "r"(b[1]),
          "f"(c[0]), "f"(c[1]), "f"(c[2]), "f"(c[3]));
}

// ---------------------------------------------------------------------------
// tf32 tensor-core GEMM NT: C[M,N] = A[M,K] * B[N,K]^T  (row-major fp32 I/O)
// 128x128 tile, BK=16, 256 threads (8 warps as 4m x 2n), warp tile 32x64.
// ---------------------------------------------------------------------------
#define GBK  16
#define GPAD 20

__global__ __launch_bounds__(256, 2) void gemm_tf32(
    const float* __restrict__ A, const float* __restrict__ Bm,
    float* __restrict__ C, int M, int N, int K)
{
    __shared__ uint32_t As[128][GPAD];
    __shared__ uint32_t Bs[128][GPAD];

    const int tid = threadIdx.x;
    const int lane = tid & 31;
    const int wid = tid >> 5;
    const int g = lane >> 2;          // group id 0..7
    const int t = lane & 3;           // thread-in-group 0..3
    const int wm = (wid >> 1) * 32;   // warp m offset: 0,32,64,96
    const int wn = (wid & 1) * 64;    // warp n offset: 0,64
    const int m0 = blockIdx.y * 128;
    const int n0 = blockIdx.x * 128;

    // gmem staging: 128 rows x 4 float4 per matrix = 512 float4; 2 per thread
    const int r0 = tid >> 2;          // 0..63
    const int c0 = tid & 3;           // 0..3

    const float* Ap = A + (size_t)m0 * K;
    const float* Bp = Bm + (size_t)n0 * K;

    float acc[2][8][4];
#pragma unroll
    for (int mi = 0; mi < 2; mi++)
#pragma unroll
        for (int ni = 0; ni < 8; ni++)
#pragma unroll
            for (int j = 0; j < 4; j++) acc[mi][ni][j] = 0.f;

    float4 ra0 = *(const float4*)(Ap + (size_t)r0 * K + c0 * 4);
    float4 ra1 = *(const float4*)(Ap + (size_t)(r0 + 64) * K + c0 * 4);
    float4 rb0 = *(const float4*)(Bp + (size_t)r0 * K + c0 * 4);
    float4 rb1 = *(const float4*)(Bp + (size_t)(r0 + 64) * K + c0 * 4);

    const int NT = K / GBK;
    for (int kt = 0; kt < NT; kt++) {
        // store staged registers (converted to tf32)
        As[r0][c0 * 4 + 0] = f2tf(ra0.x); As[r0][c0 * 4 + 1] = f2tf(ra0.y);
        As[r0][c0 * 4 + 2] = f2tf(ra0.z); As[r0][c0 * 4 + 3] = f2tf(ra0.w);
        As[r0 + 64][c0 * 4 + 0] = f2tf(ra1.x); As[r0 + 64][c0 * 4 + 1] = f2tf(ra1.y);
        As[r0 + 64][c0 * 4 + 2] = f2tf(ra1.z); As[r0 + 64][c0 * 4 + 3] = f2tf(ra1.w);
        Bs[r0][c0 * 4 + 0] = f2tf(rb0.x); Bs[r0][c0 * 4 + 1] = f2tf(rb0.y);
        Bs[r0][c0 * 4 + 2] = f2tf(rb0.z); Bs[r0][c0 * 4 + 3] = f2tf(rb0.w);
        Bs[r0 + 64][c0 * 4 + 0] = f2tf(rb1.x); Bs[r0 + 64][c0 * 4 + 1] = f2tf(rb1.y);
        Bs[r0 + 64][c0 * 4 + 2] = f2tf(rb1.z); Bs[r0 + 64][c0 * 4 + 3] = f2tf(rb1.w);
        __syncthreads();

        // prefetch next K-slice while computing this one
        if (kt + 1 < NT) {
            int kn = (kt + 1) * GBK;
            ra0 = *(const float4*)(Ap + (size_t)r0 * K + kn + c0 * 4);
            ra1 = *(const float4*)(Ap + (size_t)(r0 + 64) * K + kn + c0 * 4);
            rb0 = *(const float4*)(Bp + (size_t)r0 * K + kn + c0 * 4);
            rb1 = *(const float4*)(Bp + (size_t)(r0 + 64) * K + kn + c0 * 4);
        }

#pragma unroll
        for (int ks = 0; ks < 2; ks++) {
            uint32_t af[2][4];
#pragma unroll
            for (int mi = 0; mi < 2; mi++) {
                int mr = wm + mi * 16;
                af[mi][0] = As[mr + g][ks * 8 + t];
                af[mi][1] = As[mr + g + 8][ks * 8 + t];
                af[mi][2] = As[mr + g][ks * 8 + t + 4];
                af[mi][3] = As[mr + g + 8][ks * 8 + t + 4];
            }
#pragma unroll
            for (int ni = 0; ni < 8; ni++) {
                uint32_t bf[2];
                bf[0] = Bs[wn + ni * 8 + g][ks * 8 + t];
                bf[1] = Bs[wn + ni * 8 + g][ks * 8 + t + 4];
                mma_tf32(acc[0][ni], af[0], bf, acc[0][ni]);
                mma_tf32(acc[1][ni], af[1], bf, acc[1][ni]);
            }
        }
        __syncthreads();
    }

#pragma unroll
    for (int mi = 0; mi < 2; mi++)
#pragma unroll
        for (int ni = 0; ni < 8; ni++) {
            int row = m0 + wm + mi * 16 + g;
            int col = n0 + wn + ni * 8 + 2 * t;
            float2 v0 = make_float2(acc[mi][ni][0], acc[mi][ni][1]);
            float2 v1 = make_float2(acc[mi][ni][2], acc[mi][ni][3]);
            *(float2*)&C[(size_t)row * N + col] = v0;
            *(float2*)&C[(size_t)(row + 8) * N + col] = v1;
        }
}

// ---------------------------------------------------------------------------
// RoPE: interleaved pair rotation. t laid out [B,T,NH,HD]; freqs [T, HD/2].
// ---------------------------------------------------------------------------
__global__ void rope_kernel(float* __restrict__ tns,
                            const float* __restrict__ fcos,
                            const float* __restrict__ fsin,
                            int NH, int total)
{
    int i = blockIdx.x * blockDim.x + threadIdx.x;
    if (i >= total) return;
    int p = i & 63;
    int rem = i >> 6;
    int bt = rem / NH;
    int t = bt & (T_ - 1);
    float c = fcos[t * 64 + p];
    float s = fsin[t * 64 + p];
    float2 v = *(float2*)(tns + (size_t)i * 2);
    float2 r;
    r.x = v.x * c - v.y * s;
    r.y = v.x * s + v.y * c;
    *(float2*)(tns + (size_t)i * 2) = r;
}

// ---------------------------------------------------------------------------
// Flash attention, tf32 tensor cores.
// Block: 128 q-rows, 8 warps (16 rows each). KV tile = 64 keys.
// S = Q K^T via mma (Q pre-scaled by scale*log2e, ex2 softmax).
// P staged in smem (warp-private rows), PV via mma with V natural [s][hd].
// ---------------------------------------------------------------------------
#define QPAD 132
#define KPAD 132
#define VPAD 136
#define PPAD 68
#define FL_U32 (128 * QPAD + 64 * KPAD + 64 * VPAD + 128 * PPAD)
#define FL_BYTES (FL_U32 * 4)

__global__ __launch_bounds__(256, 1) void flash_tf32(
    const float* __restrict__ Q, const float* __restrict__ Kg,
    const float* __restrict__ Vg, float* __restrict__ Og)
{
    extern __shared__ uint32_t sm[];
    uint32_t (*Qs)[QPAD] = (uint32_t(*)[QPAD])sm;
    uint32_t (*Ks)[KPAD] = (uint32_t(*)[KPAD])(sm + 128 * QPAD);
    uint32_t (*Vs)[VPAD] = (uint32_t(*)[VPAD])(sm + 128 * QPAD + 64 * KPAD);
    uint32_t (*Ps)[PPAD] = (uint32_t(*)[PPAD])(sm + 128 * QPAD + 64 * KPAD + 64 * VPAD);

    const int tid = threadIdx.x;
    const int lane = tid & 31;
    const int wid = tid >> 5;
    const int g = lane >> 2;
    const int t = lane & 3;
    const int wq = wid * 16;           // warp's q-row offset in tile

    const int q0 = blockIdx.x * 128;
    const int bh = blockIdx.y;
    const int b = bh >> 5;             // / H_
    const int h = bh & 31;
    const int kvh = h >> 2;

    // fold 1/sqrt(HD) * log2(e) into Q
    const float qscale = 0.08838834764831845f * 1.4426950408889634f;

    // load Q tile (128 x 128), scaled + tf32
    for (int i = 0; i < 16; i++) {
        int idx = tid + i * 256;
        int r = idx >> 5;
        int c = idx & 31;
        const float* qp = Q + (((size_t)(b * T_ + q0 + r)) * H_ + h) * HD_ + c * 4;
        float4 v = *(const float4*)qp;
        Qs[r][c * 4 + 0] = f2tf(v.x * qscale);
        Qs[r][c * 4 + 1] = f2tf(v.y * qscale);
        Qs[r][c * 4 + 2] = f2tf(v.z * qscale);
        Qs[r][c * 4 + 3] = f2tf(v.w * qscale);
    }

    float o[16][4];
#pragma unroll
    for (int nt = 0; nt < 16; nt++)
#pragma unroll
        for (int j = 0; j < 4; j++) o[nt][j] = 0.f;

    float m0s = -1e30f, m1s = -1e30f;   // running max (rows g, g+8)
    float l0s = 0.f, l1s = 0.f;         // running sum

    for (int kt = 0; kt < T_ / 64; kt++) {
        __syncthreads();   // protect Ks/Vs (also covers first-iter Qs stores)
        // load K and V tiles (64 x 128 each)
        for (int i = 0; i < 8; i++) {
            int idx = tid + i * 256;
            int r = idx >> 5;
            int c = idx & 31;
            size_t off = (((size_t)(b * T_ + kt * 64 + r)) * KVH_ + kvh) * HD_ + c * 4;
            float4 kv = *(const float4*)(Kg + off);
            Ks[r][c * 4 + 0] = f2tf(kv.x);
            Ks[r][c * 4 + 1] = f2tf(kv.y);
            Ks[r][c * 4 + 2] = f2tf(kv.z);
            Ks[r][c * 4 + 3] = f2tf(kv.w);
            float4 vv = *(const float4*)(Vg + off);
            Vs[r][c * 4 + 0] = f2tf(vv.x);
            Vs[r][c * 4 + 1] = f2tf(vv.y);
            Vs[r][c * 4 + 2] = f2tf(vv.z);
            Vs[r][c * 4 + 3] = f2tf(vv.w);
        }
        __syncthreads();

        // S = Q K^T  (per warp: m16 x n64, k=128)
        float sv[8][4];
#pragma unroll
        for (int ni = 0; ni < 8; ni++)
#pragma unroll
            for (int j = 0; j < 4; j++) sv[ni][j] = 0.f;

#pragma unroll
        for (int ks = 0; ks < 16; ks++) {
            uint32_t af[4];
            af[0] = Qs[wq + g][ks * 8 + t];
            af[1] = Qs[wq + g + 8][ks * 8 + t];
            af[2] = Qs[wq + g][ks * 8 + t + 4];
            af[3] = Qs[wq + g + 8][ks * 8 + t + 4];
#pragma unroll
            for (int ni = 0; ni < 8; ni++) {
                uint32_t bf[2];
                bf[0] = Ks[ni * 8 + g][ks * 8 + t];
                bf[1] = Ks[ni * 8 + g][ks * 8 + t + 4];
                mma_tf32(sv[ni], af, bf, sv[ni]);
            }
        }

        // online softmax (base-2 domain). Row g -> sv[.][0..1], row g+8 -> sv[.][2..3]
        float mx0 = -1e30f, mx1 = -1e30f;
#pragma unroll
        for (int ni = 0; ni < 8; ni++) {
            mx0 = fmaxf(mx0, fmaxf(sv[ni][0], sv[ni][1]));
            mx1 = fmaxf(mx1, fmaxf(sv[ni][2], sv[ni][3]));
        }
        mx0 = fmaxf(mx0, __shfl_xor_sync(0xffffffffu, mx0, 1));
        mx0 = fmaxf(mx0, __shfl_xor_sync(0xffffffffu, mx0, 2));
        mx1 = fmaxf(mx1, __shfl_xor_sync(0xffffffffu, mx1, 1));
        mx1 = fmaxf(mx1, __shfl_xor_sync(0xffffffffu, mx1, 2));

        float mn0 = fmaxf(m0s, mx0);
        float mn1 = fmaxf(m1s, mx1);
        float alpha0 = ex2f(m0s - mn0);
        float alpha1 = ex2f(m1s - mn1);
        m0s = mn0; m1s = mn1;

        float ls0 = 0.f, ls1 = 0.f;
#pragma unroll
        for (int ni = 0; ni < 8; ni++) {
            float p0 = ex2f(sv[ni][0] - mn0);
            float p1 = ex2f(sv[ni][1] - mn0);
            float p2 = ex2f(sv[ni][2] - mn1);
            float p3 = ex2f(sv[ni][3] - mn1);
            ls0 += p0 + p1;
            ls1 += p2 + p3;
            uint2 w0 = make_uint2(f2tf(p0), f2tf(p1));
            uint2 w1 = make_uint2(f2tf(p2), f2tf(p3));
            *(uint2*)&Ps[wq + g][ni * 8 + 2 * t] = w0;
            *(uint2*)&Ps[wq + g + 8][ni * 8 + 2 * t] = w1;
        }
        ls0 += __shfl_xor_sync(0xffffffffu, ls0, 1);
        ls0 += __shfl_xor_sync(0xffffffffu, ls0, 2);
        ls1 += __shfl_xor_sync(0xffffffffu, ls1, 1);
        ls1 += __shfl_xor_sync(0xffffffffu, ls1, 2);
        l0s = l0s * alpha0 + ls0;
        l1s = l1s * alpha1 + ls1;

        // rescale O accumulators
#pragma unroll
        for (int nt = 0; nt < 16; nt++) {
            o[nt][0] *= alpha0; o[nt][1] *= alpha0;
            o[nt][2] *= alpha1; o[nt][3] *= alpha1;
        }
        __syncwarp();   // P rows are warp-private; order stores before loads

        // O += P * V  (per warp: m16 x n128, k=64)
#pragma unroll
        for (int ks = 0; ks < 8; ks++) {
            uint32_t af[4];
            af[0] = Ps[wq + g][ks * 8 + t];
            af[1] = Ps[wq + g + 8][ks * 8 + t];
            af[2] = Ps[wq + g][ks * 8 + t + 4];
            af[3] = Ps[wq + g + 8][ks * 8 + t + 4];
#pragma unroll
            for (int nt = 0; nt < 16; nt++) {
                uint32_t bf[2];
                bf[0] = Vs[ks * 8 + t][nt * 8 + g];
                bf[1] = Vs[ks * 8 + t + 4][nt * 8 + g];
                mma_tf32(o[nt], af, bf, o[nt]);
            }
        }
    }

    // normalize + write ctx [B,T, H*HD]
    float inv0 = 1.0f / l0s;
    float inv1 = 1.0f / l1s;
#pragma unroll
    for (int nt = 0; nt < 16; nt++) {
        size_t row0 = (size_t)(b * T_ + q0 + wq + g);
        size_t row1 = row0 + 8;
        int col = h * HD_ + nt * 8 + 2 * t;
        float2 v0 = make_float2(o[nt][0] * inv0, o[nt][1] * inv0);
        float2 v1 = make_float2(o[nt][2] * inv1, o[nt][3] * inv1);
        *(float2*)&Og[row0 * D_ + col] = v0;
        *(float2*)&Og[row1 * D_ + col] = v1;
    }
}

// ---------------------------------------------------------------------------
// kernel_launch
// Inputs: 0:x 1:wq 2:wk 3:wv 4:wo 5:freqs_cos 6:freqs_sin 7:start_pos
// ---------------------------------------------------------------------------
extern "C" void kernel_launch(void* const* d_in, const int* in_sizes, int n_in,
                              void* d_out, int out_size)
{
    const float* x  = (const float*)d_in[0];
    const float* wq = (const float*)d_in[1];
    const float* wk = (const float*)d_in[2];
    const float* wv = (const float*)d_in[3];
    const float* wo = (const float*)d_in[4];
    const float* fc = (const float*)d_in[5];
    const float* fs = (const float*)d_in[6];
    float* out = (float*)d_out;

    float *q, *k, *v, *ctx;
    cudaGetSymbolAddress((void**)&q,   g_q);
    cudaGetSymbolAddress((void**)&k,   g_k);
    cudaGetSymbolAddress((void**)&v,   g_v);
    cudaGetSymbolAddress((void**)&ctx, g_ctx);

    // QKV projections (tf32 tensor cores)
    {
        dim3 gq(D_ / 128, BT_ / 128);
        gemm_tf32<<<gq, 256>>>(x, wq, q, BT_, D_, D_);
        dim3 gkv((KVH_ * HD_) / 128, BT_ / 128);
        gemm_tf32<<<gkv, 256>>>(x, wk, k, BT_, KVH_ * HD_, D_);
        gemm_tf32<<<gkv, 256>>>(x, wv, v, BT_, KVH_ * HD_, D_);
    }

    // RoPE
    {
        int totq = BT_ * H_ * (HD_ / 2);
        rope_kernel<<<(totq + 255) / 256, 256>>>(q, fc, fs, H_, totq);
        int totk = BT_ * KVH_ * (HD_ / 2);
        rope_kernel<<<(totk + 255) / 256, 256>>>(k, fc, fs, KVH_, totk);
    }

    // Flash attention (tf32 tensor cores)
    {
        cudaFuncSetAttribute(flash_tf32,
                             cudaFuncAttributeMaxDynamicSharedMemorySize,
                             FL_BYTES);
        dim3 g(T_ / 128, B_ * H_);
        flash_tf32<<<g, 256, FL_BYTES>>>(q, k, v, ctx);
    }

    // Output projection
    {
        dim3 go(D_ / 128, BT_ / 128);
        gemm_tf32<<<go, 256>>>(ctx, wo, out, BT_, D_, D_);
    }
}

// round 9
// speedup vs baseline: 4.2686x; 1.1018x over previous
#include <cuda_runtime.h>
#include <cuda_bf16.h>
#include <cstdint>
#include <math.h>

// Problem constants
#define B_  2
#define T_  2048
#define D_  4096
#define H_  32
#define KVH_ 8
#define HD_ 128
#define BT_ (B_ * T_)            // 4096

// Scratch (allocation-free: __device__ globals)
__device__ float g_q[(size_t)BT_ * H_ * HD_];       // [B,T,H,HD]
__device__ float g_k[(size_t)BT_ * KVH_ * HD_];     // [B,T,KVH,HD]
__device__ float g_v[(size_t)BT_ * KVH_ * HD_];
__device__ float g_ctx[(size_t)BT_ * H_ * HD_];     // [B,T,H*HD] (tf32-rounded)
// tf32-pre-rounded operand copies
__device__ float g_xr[(size_t)BT_ * D_];
__device__ float g_wqr[(size_t)D_ * D_];
__device__ float g_wkr[(size_t)(KVH_ * HD_) * D_];
__device__ float g_wvr[(size_t)(KVH_ * HD_) * D_];
__device__ float g_wor[(size_t)D_ * D_];

// ---------------------------------------------------------------------------
// helpers
// ---------------------------------------------------------------------------
__device__ __forceinline__ uint32_t f2tf(float f) {
    uint32_t u;
    asm("cvt.rna.tf32.f32 %0, %1;" : "=r"(u) : "f"(f));
    return u;
}
__device__ __forceinline__ float f2tff(float f) { return __uint_as_float(f2tf(f)); }
__device__ __forceinline__ float ex2f(float x) {
    float y;
    asm("ex2.approx.ftz.f32 %0, %1;" : "=f"(y) : "f"(x));
    return y;
}
__device__ __forceinline__ void mma_tf32(float* d, const uint32_t* a,
                                         const uint32_t* b, const float* c) {
    asm volatile(
        "mma.sync.aligned.m16n8k8.row.col.f32.tf32.tf32.f32 "
        "{%0,%1,%2,%3}, {%4,%5,%6,%7}, {%8,%9}, {%10,%11,%12,%13};"
        : "=f"(d[0]), "=f"(d[1]), "=f"(d[2]), "=f"(d[3])
        : "r"(a[0]), "r"(a[1]), "r"(a[2]), "r"(a[3]),
          "r"(b[0]), "r"(b[1]),
          "f"(c[0]), "f"(c[1]), "f"(c[2]), "f"(c[3]));
}
__device__ __forceinline__ void cp16(void* smem_dst, const void* gmem_src) {
    uint32_t s = (uint32_t)__cvta_generic_to_shared(smem_dst);
    asm volatile("cp.async.cg.shared.global [%0], [%1], 16;" :: "r"(s), "l"(gmem_src));
}
#define CP_COMMIT() asm volatile("cp.async.commit_group;" ::: "memory")
template <int N>
__device__ __forceinline__ void cp_wait() {
    asm volatile("cp.async.wait_group %0;" :: "n"(N) : "memory");
}

// ---------------------------------------------------------------------------
// tf32 rounding pass (elementwise, float4)
// ---------------------------------------------------------------------------
__global__ void round_tf32_kernel(const float4* __restrict__ src,
                                  float4* __restrict__ dst, int n4)
{
    int i = blockIdx.x * blockDim.x + threadIdx.x;
    if (i >= n4) return;
    float4 v = src[i];
    v.x = f2tff(v.x); v.y = f2tff(v.y); v.z = f2tff(v.z); v.w = f2tff(v.w);
    dst[i] = v;
}

// ---------------------------------------------------------------------------
// tf32 GEMM NT with cp.async double buffering.
// C[M,N] = A[M,K] * B[N,K]^T ; A,B pre-rounded to tf32. 128x128 tile, BK=16.
// 256 threads (8 warps as 4m x 2n), warp tile 32x64.
// ---------------------------------------------------------------------------
#define GPAD 20

__global__ __launch_bounds__(256, 2) void gemm_tf32(
    const float* __restrict__ A, const float* __restrict__ Bm,
    float* __restrict__ C, int M, int N, int K)
{
    __shared__ alignas(16) uint32_t As[2][128][GPAD];
    __shared__ alignas(16) uint32_t Bs[2][128][GPAD];

    const int tid = threadIdx.x;
    const int lane = tid & 31;
    const int wid = tid >> 5;
    const int g = lane >> 2;
    const int t = lane & 3;
    const int wm = (wid >> 1) * 32;
    const int wn = (wid & 1) * 64;
    const int m0 = blockIdx.y * 128;
    const int n0 = blockIdx.x * 128;

    const int r0 = tid >> 2;          // 0..63
    const int c0 = tid & 3;           // 0..3

    const float* Ap = A + (size_t)m0 * K;
    const float* Bp = Bm + (size_t)n0 * K;

    float acc[2][8][4];
#pragma unroll
    for (int mi = 0; mi < 2; mi++)
#pragma unroll
        for (int ni = 0; ni < 8; ni++)
#pragma unroll
            for (int j = 0; j < 4; j++) acc[mi][ni][j] = 0.f;

    const int NT = K / 16;

    // prologue: stage 0
    {
        const float* a = Ap + (size_t)r0 * K + c0 * 4;
        const float* bp = Bp + (size_t)r0 * K + c0 * 4;
        cp16(&As[0][r0][c0 * 4], a);
        cp16(&As[0][r0 + 64][c0 * 4], a + (size_t)64 * K);
        cp16(&Bs[0][r0][c0 * 4], bp);
        cp16(&Bs[0][r0 + 64][c0 * 4], bp + (size_t)64 * K);
        CP_COMMIT();
    }

    for (int kt = 0; kt < NT; kt++) {
        if (kt + 1 < NT) {
            int s = (kt + 1) & 1;
            int ko = (kt + 1) * 16;
            const float* a = Ap + (size_t)r0 * K + ko + c0 * 4;
            const float* bp = Bp + (size_t)r0 * K + ko + c0 * 4;
            cp16(&As[s][r0][c0 * 4], a);
            cp16(&As[s][r0 + 64][c0 * 4], a + (size_t)64 * K);
            cp16(&Bs[s][r0][c0 * 4], bp);
            cp16(&Bs[s][r0 + 64][c0 * 4], bp + (size_t)64 * K);
            CP_COMMIT();
            cp_wait<1>();
        } else {
            cp_wait<0>();
        }
        __syncthreads();

        const int s = kt & 1;
#pragma unroll
        for (int ks = 0; ks < 2; ks++) {
            uint32_t af[2][4];
#pragma unroll
            for (int mi = 0; mi < 2; mi++) {
                int mr = wm + mi * 16;
                af[mi][0] = As[s][mr + g][ks * 8 + t];
                af[mi][1] = As[s][mr + g + 8][ks * 8 + t];
                af[mi][2] = As[s][mr + g][ks * 8 + t + 4];
                af[mi][3] = As[s][mr + g + 8][ks * 8 + t + 4];
            }
#pragma unroll
            for (int ni = 0; ni < 8; ni++) {
                uint32_t bf[2];
                bf[0] = Bs[s][wn + ni * 8 + g][ks * 8 + t];
                bf[1] = Bs[s][wn + ni * 8 + g][ks * 8 + t + 4];
                mma_tf32(acc[0][ni], af[0], bf, acc[0][ni]);
                mma_tf32(acc[1][ni], af[1], bf, acc[1][ni]);
            }
        }
        __syncthreads();
    }

#pragma unroll
    for (int mi = 0; mi < 2; mi++)
#pragma unroll
        for (int ni = 0; ni < 8; ni++) {
            int row = m0 + wm + mi * 16 + g;
            int col = n0 + wn + ni * 8 + 2 * t;
            float2 v0 = make_float2(acc[mi][ni][0], acc[mi][ni][1]);
            float2 v1 = make_float2(acc[mi][ni][2], acc[mi][ni][3]);
            *(float2*)&C[(size_t)row * N + col] = v0;
            *(float2*)&C[(size_t)(row + 8) * N + col] = v1;
        }
}

// ---------------------------------------------------------------------------
// RoPE (optionally tf32-round the result — used for K so flash can cp.async it)
// ---------------------------------------------------------------------------
__global__ void rope_kernel(float* __restrict__ tns,
                            const float* __restrict__ fcos,
                            const float* __restrict__ fsin,
                            int NH, int total, int rnd)
{
    int i = blockIdx.x * blockDim.x + threadIdx.x;
    if (i >= total) return;
    int p = i & 63;
    int rem = i >> 6;
    int bt = rem / NH;
    int t = bt & (T_ - 1);
    float c = fcos[t * 64 + p];
    float s = fsin[t * 64 + p];
    float2 v = *(float2*)(tns + (size_t)i * 2);
    float2 r;
    r.x = v.x * c - v.y * s;
    r.y = v.x * s + v.y * c;
    if (rnd) { r.x = f2tff(r.x); r.y = f2tff(r.y); }
    *(float2*)(tns + (size_t)i * 2) = r;
}

// ---------------------------------------------------------------------------
// Flash attention, tf32 MMA, cp.async-pipelined K (double) and V (single).
// Block: 128 q-rows, 8 warps. KV tile = 64 keys.
// K,V inputs pre-rounded to tf32 (rope / round pass); Q scaled+rounded here.
// ---------------------------------------------------------------------------
#define QPAD 132
#define KPAD 132
#define VPAD 136
#define PPAD 68
#define FL_U32 (128 * QPAD + 2 * 64 * KPAD + 64 * VPAD + 128 * PPAD)
#define FL_BYTES (FL_U32 * 4)

__global__ __launch_bounds__(256, 1) void flash_tf32(
    const float* __restrict__ Q, const float* __restrict__ Kg,
    const float* __restrict__ Vg, float* __restrict__ Og)
{
    extern __shared__ uint32_t sm[];
    uint32_t (*Qs)[QPAD] = (uint32_t(*)[QPAD])sm;
    uint32_t (*Ks)[64][KPAD] = (uint32_t(*)[64][KPAD])(sm + 128 * QPAD);
    uint32_t (*Vs)[VPAD] = (uint32_t(*)[VPAD])(sm + 128 * QPAD + 2 * 64 * KPAD);
    uint32_t (*Ps)[PPAD] = (uint32_t(*)[PPAD])(sm + 128 * QPAD + 2 * 64 * KPAD + 64 * VPAD);

    const int tid = threadIdx.x;
    const int lane = tid & 31;
    const int wid = tid >> 5;
    const int g = lane >> 2;
    const int t = lane & 3;
    const int wq = wid * 16;

    const int q0 = blockIdx.x * 128;
    const int bh = blockIdx.y;
    const int b = bh >> 5;
    const int h = bh & 31;
    const int kvh = h >> 2;

    const float qscale = 0.08838834764831845f * 1.4426950408889634f;

    const float* Kbase = Kg + (((size_t)b * T_) * KVH_ + kvh) * HD_;
    const float* Vbase = Vg + (((size_t)b * T_) * KVH_ + kvh) * HD_;

    // prologue: K(0) then V(0) in flight
    {
#pragma unroll
        for (int i = 0; i < 8; i++) {
            int idx = tid + i * 256;
            int r = idx >> 5;
            int ch = idx & 31;
            cp16(&Ks[0][r][ch * 4], Kbase + (size_t)r * (KVH_ * HD_) + ch * 4);
        }
        CP_COMMIT();
#pragma unroll
        for (int i = 0; i < 8; i++) {
            int idx = tid + i * 256;
            int r = idx >> 5;
            int ch = idx & 31;
            cp16(&Vs[r][ch * 4], Vbase + (size_t)r * (KVH_ * HD_) + ch * 4);
        }
        CP_COMMIT();
    }

    // Q tile (128 x 128): scale + tf32-round into smem
    for (int i = 0; i < 16; i++) {
        int idx = tid + i * 256;
        int r = idx >> 5;
        int c = idx & 31;
        const float* qp = Q + (((size_t)(b * T_ + q0 + r)) * H_ + h) * HD_ + c * 4;
        float4 v = *(const float4*)qp;
        Qs[r][c * 4 + 0] = f2tf(v.x * qscale);
        Qs[r][c * 4 + 1] = f2tf(v.y * qscale);
        Qs[r][c * 4 + 2] = f2tf(v.z * qscale);
        Qs[r][c * 4 + 3] = f2tf(v.w * qscale);
    }

    float o[16][4];
#pragma unroll
    for (int nt = 0; nt < 16; nt++)
#pragma unroll
        for (int j = 0; j < 4; j++) o[nt][j] = 0.f;

    float m0s = -1e30f, m1s = -1e30f;
    float l0s = 0.f, l1s = 0.f;

    const int NKT = T_ / 64;
    for (int kt = 0; kt < NKT; kt++) {
        const int s = kt & 1;
        cp_wait<1>();        // K(kt) complete (V(kt) may still be in flight)
        __syncthreads();

        // S = Q K^T  (per warp: m16 x n64, k=128)
        float sv[8][4];
#pragma unroll
        for (int ni = 0; ni < 8; ni++)
#pragma unroll
            for (int j = 0; j < 4; j++) sv[ni][j] = 0.f;

#pragma unroll
        for (int ks = 0; ks < 16; ks++) {
            uint32_t af[4];
            af[0] = Qs[wq + g][ks * 8 + t];
            af[1] = Qs[wq + g + 8][ks * 8 + t];
            af[2] = Qs[wq + g][ks * 8 + t + 4];
            af[3] = Qs[wq + g + 8][ks * 8 + t + 4];
#pragma unroll
            for (int ni = 0; ni < 8; ni++) {
                uint32_t bf[2];
                bf[0] = Ks[s][ni * 8 + g][ks * 8 + t];
                bf[1] = Ks[s][ni * 8 + g][ks * 8 + t + 4];
                mma_tf32(sv[ni], af, bf, sv[ni]);
            }
        }

        // online softmax (base-2)
        float mx0 = -1e30f, mx1 = -1e30f;
#pragma unroll
        for (int ni = 0; ni < 8; ni++) {
            mx0 = fmaxf(mx0, fmaxf(sv[ni][0], sv[ni][1]));
            mx1 = fmaxf(mx1, fmaxf(sv[ni][2], sv[ni][3]));
        }
        mx0 = fmaxf(mx0, __shfl_xor_sync(0xffffffffu, mx0, 1));
        mx0 = fmaxf(mx0, __shfl_xor_sync(0xffffffffu, mx0, 2));
        mx1 = fmaxf(mx1, __shfl_xor_sync(0xffffffffu, mx1, 1));
        mx1 = fmaxf(mx1, __shfl_xor_sync(0xffffffffu, mx1, 2));

        float mn0 = fmaxf(m0s, mx0);
        float mn1 = fmaxf(m1s, mx1);
        float alpha0 = ex2f(m0s - mn0);
        float alpha1 = ex2f(m1s - mn1);
        m0s = mn0; m1s = mn1;

        float ls0 = 0.f, ls1 = 0.f;
#pragma unroll
        for (int ni = 0; ni < 8; ni++) {
            float p0 = ex2f(sv[ni][0] - mn0);
            float p1 = ex2f(sv[ni][1] - mn0);
            float p2 = ex2f(sv[ni][2] - mn1);
            float p3 = ex2f(sv[ni][3] - mn1);
            ls0 += p0 + p1;
            ls1 += p2 + p3;
            uint2 w0 = make_uint2(f2tf(p0), f2tf(p1));
            uint2 w1 = make_uint2(f2tf(p2), f2tf(p3));
            *(uint2*)&Ps[wq + g][ni * 8 + 2 * t] = w0;
            *(uint2*)&Ps[wq + g + 8][ni * 8 + 2 * t] = w1;
        }
        ls0 += __shfl_xor_sync(0xffffffffu, ls0, 1);
        ls0 += __shfl_xor_sync(0xffffffffu, ls0, 2);
        ls1 += __shfl_xor_sync(0xffffffffu, ls1, 1);
        ls1 += __shfl_xor_sync(0xffffffffu, ls1, 2);
        l0s = l0s * alpha0 + ls0;
        l1s = l1s * alpha1 + ls1;

#pragma unroll
        for (int nt = 0; nt < 16; nt++) {
            o[nt][0] *= alpha0; o[nt][1] *= alpha0;
            o[nt][2] *= alpha1; o[nt][3] *= alpha1;
        }

        cp_wait<0>();        // V(kt) complete
        __syncthreads();     // visibility of all threads' V chunks (+ Ps warp-private)

        // launch K(kt+1) while PV runs
        if (kt + 1 < NKT) {
            const float* kp = Kbase + (size_t)(kt + 1) * 64 * (KVH_ * HD_);
#pragma unroll
            for (int i = 0; i < 8; i++) {
                int idx = tid + i * 256;
                int r = idx >> 5;
                int ch = idx & 31;
                cp16(&Ks[s ^ 1][r][ch * 4], kp + (size_t)r * (KVH_ * HD_) + ch * 4);
            }
            CP_COMMIT();
        }

        // O += P * V
#pragma unroll
        for (int ks = 0; ks < 8; ks++) {
            uint32_t af[4];
            af[0] = Ps[wq + g][ks * 8 + t];
            af[1] = Ps[wq + g + 8][ks * 8 + t];
            af[2] = Ps[wq + g][ks * 8 + t + 4];
            af[3] = Ps[wq + g + 8][ks * 8 + t + 4];
#pragma unroll
            for (int nt = 0; nt < 16; nt++) {
                uint32_t bf[2];
                bf[0] = Vs[ks * 8 + t][nt * 8 + g];
                bf[1] = Vs[ks * 8 + t + 4][nt * 8 + g];
                mma_tf32(o[nt], af, bf, o[nt]);
            }
        }
        __syncthreads();     // all warps done reading Vs

        // launch V(kt+1)
        if (kt + 1 < NKT) {
            const float* vp = Vbase + (size_t)(kt + 1) * 64 * (KVH_ * HD_);
#pragma unroll
            for (int i = 0; i < 8; i++) {
                int idx = tid + i * 256;
                int r = idx >> 5;
                int ch = idx & 31;
                cp16(&Vs[r][ch * 4], vp + (size_t)r * (KVH_ * HD_) + ch * 4);
            }
            CP_COMMIT();
        }
    }

    // normalize + write ctx (tf32-rounded so O-proj can cp.async it)
    float inv0 = 1.0f / l0s;
    float inv1 = 1.0f / l1s;
#pragma unroll
    for (int nt = 0; nt < 16; nt++) {
        size_t row0 = (size_t)(b * T_ + q0 + wq + g);
        size_t row1 = row0 + 8;
        int col = h * HD_ + nt * 8 + 2 * t;
        float2 v0 = make_float2(f2tff(o[nt][0] * inv0), f2tff(o[nt][1] * inv0));
        float2 v1 = make_float2(f2tff(o[nt][2] * inv1), f2tff(o[nt][3] * inv1));
        *(float2*)&Og[row0 * D_ + col] = v0;
        *(float2*)&Og[row1 * D_ + col] = v1;
    }
}

// ---------------------------------------------------------------------------
// kernel_launch
// Inputs: 0:x 1:wq 2:wk 3:wv 4:wo 5:freqs_cos 6:freqs_sin 7:start_pos
// ---------------------------------------------------------------------------
extern "C" void kernel_launch(void* const* d_in, const int* in_sizes, int n_in,
                              void* d_out, int out_size)
{
    const float* x  = (const float*)d_in[0];
    const float* wq = (const float*)d_in[1];
    const float* wk = (const float*)d_in[2];
    const float* wv = (const float*)d_in[3];
    const float* wo = (const float*)d_in[4];
    const float* fc = (const float*)d_in[5];
    const float* fs = (const float*)d_in[6];
    float* out = (float*)d_out;

    float *q, *k, *v, *ctx, *xr, *wqr, *wkr, *wvr, *wor;
    cudaGetSymbolAddress((void**)&q,   g_q);
    cudaGetSymbolAddress((void**)&k,   g_k);
    cudaGetSymbolAddress((void**)&v,   g_v);
    cudaGetSymbolAddress((void**)&ctx, g_ctx);
    cudaGetSymbolAddress((void**)&xr,  g_xr);
    cudaGetSymbolAddress((void**)&wqr, g_wqr);
    cudaGetSymbolAddress((void**)&wkr, g_wkr);
    cudaGetSymbolAddress((void**)&wvr, g_wvr);
    cudaGetSymbolAddress((void**)&wor, g_wor);

    // pre-round GEMM operands to tf32
    {
        int n4x = BT_ * D_ / 4;
        round_tf32_kernel<<<(n4x + 255) / 256, 256>>>((const float4*)x,  (float4*)xr,  n4x);
        int n4q = D_ * D_ / 4;
        round_tf32_kernel<<<(n4q + 255) / 256, 256>>>((const float4*)wq, (float4*)wqr, n4q);
        int n4k = (KVH_ * HD_) * D_ / 4;
        round_tf32_kernel<<<(n4k + 255) / 256, 256>>>((const float4*)wk, (float4*)wkr, n4k);
        round_tf32_kernel<<<(n4k + 255) / 256, 256>>>((const float4*)wv, (float4*)wvr, n4k);
        round_tf32_kernel<<<(n4q + 255) / 256, 256>>>((const float4*)wo, (float4*)wor, n4q);
    }

    // QKV projections
    {
        dim3 gq(D_ / 128, BT_ / 128);
        gemm_tf32<<<gq, 256>>>(xr, wqr, q, BT_, D_, D_);
        dim3 gkv((KVH_ * HD_) / 128, BT_ / 128);
        gemm_tf32<<<gkv, 256>>>(xr, wkr, k, BT_, KVH_ * HD_, D_);
        gemm_tf32<<<gkv, 256>>>(xr, wvr, v, BT_, KVH_ * HD_, D_);
    }

    // RoPE (K rounded to tf32 for flash cp.async); V rounded separately
    {
        int totq = BT_ * H_ * (HD_ / 2);
        rope_kernel<<<(totq + 255) / 256, 256>>>(q, fc, fs, H_, totq, 0);
        int totk = BT_ * KVH_ * (HD_ / 2);
        rope_kernel<<<(totk + 255) / 256, 256>>>(k, fc, fs, KVH_, totk, 1);
        int n4v = BT_ * KVH_ * HD_ / 4;
        round_tf32_kernel<<<(n4v + 255) / 256, 256>>>((const float4*)v, (float4*)v, n4v);
    }

    // Flash attention
    {
        cudaFuncSetAttribute(flash_tf32,
                             cudaFuncAttributeMaxDynamicSharedMemorySize,
                             FL_BYTES);
        dim3 g(T_ / 128, B_ * H_);
        flash_tf32<<<g, 256, FL_BYTES>>>(q, k, v, ctx);
    }

    // Output projection
    {
        dim3 go(D_ / 128, BT_ / 128);
        gemm_tf32<<<go, 256>>>(ctx, wor, out, BT_, D_, D_);
    }
}

// round 12
// speedup vs baseline: 7.8335x; 1.8351x over previous
#include <cuda_runtime.h>
#include <cuda_fp16.h>
#include <cstdint>
#include <math.h>

// Problem constants
#define B_  2
#define T_  2048
#define D_  4096
#define H_  32
#define KVH_ 8
#define HD_ 128
#define BT_ (B_ * T_)            // 4096

// Scratch (allocation-free: __device__ globals) — fp16 pipeline
__device__ __half g_qh[(size_t)BT_ * H_ * HD_];     // [B,T,H,HD]
__device__ __half g_kh[(size_t)BT_ * KVH_ * HD_];   // [B,T,KVH,HD]
__device__ __half g_vh[(size_t)BT_ * KVH_ * HD_];
__device__ __half g_ctxh[(size_t)BT_ * H_ * HD_];   // [B,T,H*HD]
__device__ __half g_xh[(size_t)BT_ * D_];
__device__ __half g_wqh[(size_t)D_ * D_];
__device__ __half g_wkh[(size_t)(KVH_ * HD_) * D_];
__device__ __half g_wvh[(size_t)(KVH_ * HD_) * D_];
__device__ __half g_woh[(size_t)D_ * D_];

// ---------------------------------------------------------------------------
// helpers
// ---------------------------------------------------------------------------
__device__ __forceinline__ float ex2f(float x) {
    float y;
    asm("ex2.approx.ftz.f32 %0, %1;" : "=f"(y) : "f"(x));
    return y;
}
// D(16x8,f32) = A(16x16,f16) * B(16x8,f16,col) + C
__device__ __forceinline__ void mma_f16(float* d, const uint32_t* a,
                                        const uint32_t* b, const float* c) {
    asm volatile(
        "mma.sync.aligned.m16n8k16.row.col.f32.f16.f16.f32 "
        "{%0,%1,%2,%3}, {%4,%5,%6,%7}, {%8,%9}, {%10,%11,%12,%13};"
        : "=f"(d[0]), "=f"(d[1]), "=f"(d[2]), "=f"(d[3])
        : "r"(a[0]), "r"(a[1]), "r"(a[2]), "r"(a[3]),
          "r"(b[0]), "r"(b[1]),
          "f"(c[0]), "f"(c[1]), "f"(c[2]), "f"(c[3]));
}
__device__ __forceinline__ void ldsm_x4_t(uint32_t& r0, uint32_t& r1,
                                          uint32_t& r2, uint32_t& r3, uint32_t addr) {
    asm volatile("ldmatrix.sync.aligned.m8n8.x4.trans.shared.b16 {%0,%1,%2,%3}, [%4];"
                 : "=r"(r0), "=r"(r1), "=r"(r2), "=r"(r3) : "r"(addr));
}
__device__ __forceinline__ void cp16s(uint32_t saddr, const void* gmem_src) {
    asm volatile("cp.async.cg.shared.global [%0], [%1], 16;" :: "r"(saddr), "l"(gmem_src));
}
#define CP_COMMIT() asm volatile("cp.async.commit_group;" ::: "memory")
template <int N>
__device__ __forceinline__ void cp_wait() {
    asm volatile("cp.async.wait_group %0;" :: "n"(N) : "memory");
}
__device__ __forceinline__ uint32_t smem_u32(const void* p) {
    return (uint32_t)__cvta_generic_to_shared(p);
}
__device__ __forceinline__ uint32_t pack_h2(float a, float b) {
    __half2 h = __floats2half2_rn(a, b);
    return *(uint32_t*)&h;
}

// ---------------------------------------------------------------------------
// fp32 -> fp16 conversion pass
// ---------------------------------------------------------------------------
__global__ void f2h_kernel(const float4* __restrict__ src,
                           uint2* __restrict__ dst, int n4)
{
    int i = blockIdx.x * blockDim.x + threadIdx.x;
    if (i >= n4) return;
    float4 v = src[i];
    uint2 o;
    o.x = pack_h2(v.x, v.y);
    o.y = pack_h2(v.z, v.w);
    dst[i] = o;
}

// ---------------------------------------------------------------------------
// fp16 GEMM NT: C[M,N] = A[M,K] * B[N,K]^T (half in, fp32 accum).
// 128x128 tile, BK=32, 2-stage cp.async. 256 threads (8 warps, 4m x 2n),
// warp tile 32x64 via m16n8k16. out_half: write half, else fp32.
// ---------------------------------------------------------------------------
#define GW 20   // 32-bit words per smem row (32 data halfs + 8 pad)

__global__ __launch_bounds__(256) void gemm_h(
    const __half* __restrict__ A, const __half* __restrict__ Bm,
    void* __restrict__ Cout, int M, int N, int K, int out_half)
{
    __shared__ alignas(16) uint32_t As[2][128 * GW];
    __shared__ alignas(16) uint32_t Bs[2][128 * GW];

    const int tid = threadIdx.x;
    const int lane = tid & 31;
    const int wid = tid >> 5;
    const int g = lane >> 2;
    const int t = lane & 3;
    const int wm = (wid >> 1) * 32;
    const int wn = (wid & 1) * 64;
    const int m0 = blockIdx.y * 128;
    const int n0 = blockIdx.x * 128;

    const __half* Ap = A + (size_t)m0 * K;
    const __half* Bp = Bm + (size_t)n0 * K;

    float acc[2][8][4];
#pragma unroll
    for (int mi = 0; mi < 2; mi++)
#pragma unroll
        for (int ni = 0; ni < 8; ni++)
#pragma unroll
            for (int j = 0; j < 4; j++) acc[mi][ni][j] = 0.f;

    const int NT = K / 32;

    // stage loader: A,B 128 rows x 32 halfs (4 x 16B chunks per row)
    auto load_stage = [&](int s, int kt) {
        uint32_t ab = smem_u32(&As[s][0]);
        uint32_t bb = smem_u32(&Bs[s][0]);
#pragma unroll
        for (int i = 0; i < 2; i++) {
            int idx = tid + i * 256;
            int row = idx >> 2;
            int ch = idx & 3;
            cp16s(ab + row * (GW * 4) + ch * 16, Ap + (size_t)row * K + kt * 32 + ch * 8);
            cp16s(bb + row * (GW * 4) + ch * 16, Bp + (size_t)row * K + kt * 32 + ch * 8);
        }
    };

    load_stage(0, 0);
    CP_COMMIT();

    for (int kt = 0; kt < NT; kt++) {
        if (kt + 1 < NT) {
            load_stage((kt + 1) & 1, kt + 1);
            CP_COMMIT();
            cp_wait<1>();
        } else {
            cp_wait<0>();
        }
        __syncthreads();

        const int s = kt & 1;
#pragma unroll
        for (int ks = 0; ks < 2; ks++) {
            uint32_t af[2][4];
#pragma unroll
            for (int mi = 0; mi < 2; mi++) {
                int mr = wm + mi * 16;
                af[mi][0] = As[s][(mr + g) * GW + ks * 8 + t];
                af[mi][1] = As[s][(mr + g + 8) * GW + ks * 8 + t];
                af[mi][2] = As[s][(mr + g) * GW + ks * 8 + t + 4];
                af[mi][3] = As[s][(mr + g + 8) * GW + ks * 8 + t + 4];
            }
#pragma unroll
            for (int ni = 0; ni < 8; ni++) {
                uint32_t bf[2];
                bf[0] = Bs[s][(wn + ni * 8 + g) * GW + ks * 8 + t];
                bf[1] = Bs[s][(wn + ni * 8 + g) * GW + ks * 8 + t + 4];
                mma_f16(acc[0][ni], af[0], bf, acc[0][ni]);
                mma_f16(acc[1][ni], af[1], bf, acc[1][ni]);
            }
        }
        __syncthreads();
    }

    if (out_half) {
        __half* Ch = (__half*)Cout;
#pragma unroll
        for (int mi = 0; mi < 2; mi++)
#pragma unroll
            for (int ni = 0; ni < 8; ni++) {
                int row = m0 + wm + mi * 16 + g;
                int col = n0 + wn + ni * 8 + 2 * t;
                *(uint32_t*)&Ch[(size_t)row * N + col] = pack_h2(acc[mi][ni][0], acc[mi][ni][1]);
                *(uint32_t*)&Ch[(size_t)(row + 8) * N + col] = pack_h2(acc[mi][ni][2], acc[mi][ni][3]);
            }
    } else {
        float* Cf = (float*)Cout;
#pragma unroll
        for (int mi = 0; mi < 2; mi++)
#pragma unroll
            for (int ni = 0; ni < 8; ni++) {
                int row = m0 + wm + mi * 16 + g;
                int col = n0 + wn + ni * 8 + 2 * t;
                *(float2*)&Cf[(size_t)row * N + col] = make_float2(acc[mi][ni][0], acc[mi][ni][1]);
                *(float2*)&Cf[(size_t)(row + 8) * N + col] = make_float2(acc[mi][ni][2], acc[mi][ni][3]);
            }
    }
}

// ---------------------------------------------------------------------------
// RoPE on half data: one thread per (b,t,h,pair)
// ---------------------------------------------------------------------------
__global__ void rope_h_kernel(__half2* __restrict__ tns,
                              const float* __restrict__ fcos,
                              const float* __restrict__ fsin,
                              int NH, int total)
{
    int i = blockIdx.x * blockDim.x + threadIdx.x;
    if (i >= total) return;
    int p = i & 63;
    int rem = i >> 6;
    int bt = rem / NH;
    int t = bt & (T_ - 1);
    float c = fcos[t * 64 + p];
    float s = fsin[t * 64 + p];
    float2 v = __half22float2(tns[i]);
    tns[i] = __floats2half2_rn(v.x * c - v.y * s, v.x * s + v.y * c);
}

// ---------------------------------------------------------------------------
// Flash attention, fp16 mma.m16n8k16.
// Block: 128 q-rows, 8 warps (16 each). KV tile 64 keys.
// Q cp.async'd once; K double-buffered; V single-buffered (ldmatrix.trans).
// Scale applied to fp32 scores post-MMA (base-2 softmax).
// ---------------------------------------------------------------------------
#define QW 68    // words per Q/K/V smem row (128 halfs data + 8 pad)
#define PW 36    // words per P row (64 halfs data + 8 pad)
#define FL_WORDS (128 * QW + 2 * 64 * QW + 64 * QW + 128 * PW)
#define FL_BYTES (FL_WORDS * 4)

__global__ __launch_bounds__(256, 1) void flash_h(
    const __half* __restrict__ Q, const __half* __restrict__ Kg,
    const __half* __restrict__ Vg, __half* __restrict__ Og)
{
    extern __shared__ uint32_t sm[];
    uint32_t* Qs = sm;                          // 128 x QW
    uint32_t* Ks = sm + 128 * QW;               // 2 x 64 x QW
    uint32_t* Vs = Ks + 2 * 64 * QW;            // 64 x QW
    uint32_t* Ps = Vs + 64 * QW;                // 128 x PW

    const int tid = threadIdx.x;
    const int lane = tid & 31;
    const int wid = tid >> 5;
    const int g = lane >> 2;
    const int t = lane & 3;
    const int wq = wid * 16;

    const int q0 = blockIdx.x * 128;
    const int bh = blockIdx.y;
    const int b = bh >> 5;
    const int h = bh & 31;
    const int kvh = h >> 2;

    const float qs = 0.08838834764831845f * 1.4426950408889634f;  // scale*log2e

    const __half* Qb = Q + (((size_t)(b * T_ + q0)) * H_ + h) * HD_;
    const __half* Kb = Kg + (((size_t)b * T_) * KVH_ + kvh) * HD_;
    const __half* Vb = Vg + (((size_t)b * T_) * KVH_ + kvh) * HD_;

    const uint32_t qsb = smem_u32(Qs);
    const uint32_t ksb = smem_u32(Ks);
    const uint32_t vsb = smem_u32(Vs);

    // prologue: Q (group), K0 (group), V0 (group)
    {
#pragma unroll
        for (int i = 0; i < 8; i++) {     // 128 rows x 16 chunks
            int idx = tid + i * 256;
            int r = idx >> 4;
            int ch = idx & 15;
            cp16s(qsb + r * (QW * 4) + ch * 16, Qb + (size_t)r * (H_ * HD_) + ch * 8);
        }
        CP_COMMIT();
#pragma unroll
        for (int i = 0; i < 4; i++) {     // 64 rows x 16 chunks
            int idx = tid + i * 256;
            int r = idx >> 4;
            int ch = idx & 15;
            cp16s(ksb + r * (QW * 4) + ch * 16, Kb + (size_t)r * (KVH_ * HD_) + ch * 8);
        }
        CP_COMMIT();
#pragma unroll
        for (int i = 0; i < 4; i++) {
            int idx = tid + i * 256;
            int r = idx >> 4;
            int ch = idx & 15;
            cp16s(vsb + r * (QW * 4) + ch * 16, Vb + (size_t)r * (KVH_ * HD_) + ch * 8);
        }
        CP_COMMIT();
    }

    float o[16][4];
#pragma unroll
    for (int nt = 0; nt < 16; nt++)
#pragma unroll
        for (int j = 0; j < 4; j++) o[nt][j] = 0.f;

    float m0s = -1e30f, m1s = -1e30f;
    float l0s = 0.f, l1s = 0.f;

    const int NKT = T_ / 64;
    for (int kt = 0; kt < NKT; kt++) {
        const int s = kt & 1;
        const uint32_t* Kcur = Ks + s * 64 * QW;
        cp_wait<1>();      // Q + K(kt) resident (V(kt) may be in flight)
        __syncthreads();

        // S = Q K^T : per warp m16 x n64, k=128 (8 k16 steps)
        float sv[8][4];
#pragma unroll
        for (int ni = 0; ni < 8; ni++)
#pragma unroll
            for (int j = 0; j < 4; j++) sv[ni][j] = 0.f;

#pragma unroll
        for (int ks = 0; ks < 8; ks++) {
            uint32_t af[4];
            af[0] = Qs[(wq + g) * QW + ks * 8 + t];
            af[1] = Qs[(wq + g + 8) * QW + ks * 8 + t];
            af[2] = Qs[(wq + g) * QW + ks * 8 + t + 4];
            af[3] = Qs[(wq + g + 8) * QW + ks * 8 + t + 4];
#pragma unroll
            for (int ni = 0; ni < 8; ni++) {
                uint32_t bf[2];
                bf[0] = Kcur[(ni * 8 + g) * QW + ks * 8 + t];
                bf[1] = Kcur[(ni * 8 + g) * QW + ks * 8 + t + 4];
                mma_f16(sv[ni], af, bf, sv[ni]);
            }
        }

        // scale + online softmax (base-2)
        float mx0 = -1e30f, mx1 = -1e30f;
#pragma unroll
        for (int ni = 0; ni < 8; ni++) {
            sv[ni][0] *= qs; sv[ni][1] *= qs; sv[ni][2] *= qs; sv[ni][3] *= qs;
            mx0 = fmaxf(mx0, fmaxf(sv[ni][0], sv[ni][1]));
            mx1 = fmaxf(mx1, fmaxf(sv[ni][2], sv[ni][3]));
        }
        mx0 = fmaxf(mx0, __shfl_xor_sync(0xffffffffu, mx0, 1));
        mx0 = fmaxf(mx0, __shfl_xor_sync(0xffffffffu, mx0, 2));
        mx1 = fmaxf(mx1, __shfl_xor_sync(0xffffffffu, mx1, 1));
        mx1 = fmaxf(mx1, __shfl_xor_sync(0xffffffffu, mx1, 2));

        float mn0 = fmaxf(m0s, mx0);
        float mn1 = fmaxf(m1s, mx1);
        float alpha0 = ex2f(m0s - mn0);
        float alpha1 = ex2f(m1s - mn1);
        m0s = mn0; m1s = mn1;

        float ls0 = 0.f, ls1 = 0.f;
#pragma unroll
        for (int ni = 0; ni < 8; ni++) {
            float p0 = ex2f(sv[ni][0] - mn0);
            float p1 = ex2f(sv[ni][1] - mn0);
            float p2 = ex2f(sv[ni][2] - mn1);
            float p3 = ex2f(sv[ni][3] - mn1);
            ls0 += p0 + p1;
            ls1 += p2 + p3;
            Ps[(wq + g) * PW + ni * 4 + t] = pack_h2(p0, p1);
            Ps[(wq + g + 8) * PW + ni * 4 + t] = pack_h2(p2, p3);
        }
        ls0 += __shfl_xor_sync(0xffffffffu, ls0, 1);
        ls0 += __shfl_xor_sync(0xffffffffu, ls0, 2);
        ls1 += __shfl_xor_sync(0xffffffffu, ls1, 1);
        ls1 += __shfl_xor_sync(0xffffffffu, ls1, 2);
        l0s = l0s * alpha0 + ls0;
        l1s = l1s * alpha1 + ls1;

#pragma unroll
        for (int nt = 0; nt < 16; nt++) {
            o[nt][0] *= alpha0; o[nt][1] *= alpha0;
            o[nt][2] *= alpha1; o[nt][3] *= alpha1;
        }

        cp_wait<0>();      // V(kt) resident
        __syncthreads();   // V visible to all; Ps warp-private rows ordered by __syncwarp semantics of mma path

        // launch K(kt+1) while PV runs
        if (kt + 1 < NKT) {
            const __half* kp = Kb + (size_t)(kt + 1) * 64 * (KVH_ * HD_);
            uint32_t kdst = ksb + (s ^ 1) * 64 * QW * 4;
#pragma unroll
            for (int i = 0; i < 4; i++) {
                int idx = tid + i * 256;
                int r = idx >> 4;
                int ch = idx & 15;
                cp16s(kdst + r * (QW * 4) + ch * 16, kp + (size_t)r * (KVH_ * HD_) + ch * 8);
            }
            CP_COMMIT();
        }

        // O += P * V : per warp m16 x n128, k=64 (4 k16 steps)
        {
            const int sub = lane >> 3;        // 0..3
            const int rr = lane & 7;          // 0..7
#pragma unroll
            for (int ks = 0; ks < 4; ks++) {
                uint32_t af[4];
                af[0] = Ps[(wq + g) * PW + ks * 8 + t];
                af[1] = Ps[(wq + g + 8) * PW + ks * 8 + t];
                af[2] = Ps[(wq + g) * PW + ks * 8 + t + 4];
                af[3] = Ps[(wq + g + 8) * PW + ks * 8 + t + 4];
#pragma unroll
                for (int ntp = 0; ntp < 8; ntp++) {
                    // ldmatrix x4 trans: 4 tiles (k-low/k-high) x (nt even/odd)
                    int rowa = ks * 16 + rr + (sub & 1) * 8;
                    int cola = ntp * 16 + (sub >> 1) * 8;
                    uint32_t addr = vsb + rowa * (QW * 4) + cola * 2;
                    uint32_t b0, b1, b2, b3;
                    ldsm_x4_t(b0, b1, b2, b3, addr);
                    uint32_t be[2] = {b0, b1};
                    uint32_t bo[2] = {b2, b3};
                    mma_f16(o[2 * ntp], af, be, o[2 * ntp]);
                    mma_f16(o[2 * ntp + 1], af, bo, o[2 * ntp + 1]);
                }
            }
        }
        __syncthreads();   // all warps done reading Vs

        // launch V(kt+1)
        if (kt + 1 < NKT) {
            const __half* vp = Vb + (size_t)(kt + 1) * 64 * (KVH_ * HD_);
#pragma unroll
            for (int i = 0; i < 4; i++) {
                int idx = tid + i * 256;
                int r = idx >> 4;
                int ch = idx & 15;
                cp16s(vsb + r * (QW * 4) + ch * 16, vp + (size_t)r * (KVH_ * HD_) + ch * 8);
            }
            CP_COMMIT();
        }
    }

    // normalize + write ctx (half) [B,T,H*HD]
    float inv0 = 1.0f / l0s;
    float inv1 = 1.0f / l1s;
#pragma unroll
    for (int nt = 0; nt < 16; nt++) {
        size_t row0 = (size_t)(b * T_ + q0 + wq + g);
        size_t row1 = row0 + 8;
        int col = h * HD_ + nt * 8 + 2 * t;
        *(uint32_t*)&Og[row0 * D_ + col] = pack_h2(o[nt][0] * inv0, o[nt][1] * inv0);
        *(uint32_t*)&Og[row1 * D_ + col] = pack_h2(o[nt][2] * inv1, o[nt][3] * inv1);
    }
}

// ---------------------------------------------------------------------------
// kernel_launch
// Inputs: 0:x 1:wq 2:wk 3:wv 4:wo 5:freqs_cos 6:freqs_sin 7:start_pos
// ---------------------------------------------------------------------------
extern "C" void kernel_launch(void* const* d_in, const int* in_sizes, int n_in,
                              void* d_out, int out_size)
{
    const float* x  = (const float*)d_in[0];
    const float* wq = (const float*)d_in[1];
    const float* wk = (const float*)d_in[2];
    const float* wv = (const float*)d_in[3];
    const float* wo = (const float*)d_in[4];
    const float* fc = (const float*)d_in[5];
    const float* fs = (const float*)d_in[6];
    float* out = (float*)d_out;

    __half *qh, *kh, *vh, *ctxh, *xh, *wqh, *wkh, *wvh, *woh;
    cudaGetSymbolAddress((void**)&qh,   g_qh);
    cudaGetSymbolAddress((void**)&kh,   g_kh);
    cudaGetSymbolAddress((void**)&vh,   g_vh);
    cudaGetSymbolAddress((void**)&ctxh, g_ctxh);
    cudaGetSymbolAddress((void**)&xh,   g_xh);
    cudaGetSymbolAddress((void**)&wqh,  g_wqh);
    cudaGetSymbolAddress((void**)&wkh,  g_wkh);
    cudaGetSymbolAddress((void**)&wvh,  g_wvh);
    cudaGetSymbolAddress((void**)&woh,  g_woh);

    cudaFuncSetAttribute(flash_h,
                         cudaFuncAttributeMaxDynamicSharedMemorySize, FL_BYTES);

    // convert inputs to fp16
    {
        int n4x = BT_ * D_ / 4;
        f2h_kernel<<<(n4x + 255) / 256, 256>>>((const float4*)x,  (uint2*)xh,  n4x);
        int n4q = D_ * D_ / 4;
        f2h_kernel<<<(n4q + 255) / 256, 256>>>((const float4*)wq, (uint2*)wqh, n4q);
        int n4k = (KVH_ * HD_) * D_ / 4;
        f2h_kernel<<<(n4k + 255) / 256, 256>>>((const float4*)wk, (uint2*)wkh, n4k);
        f2h_kernel<<<(n4k + 255) / 256, 256>>>((const float4*)wv, (uint2*)wvh, n4k);
        f2h_kernel<<<(n4q + 255) / 256, 256>>>((const float4*)wo, (uint2*)woh, n4q);
    }

    // QKV projections (fp16 in/out, fp32 accum)
    {
        dim3 gq(D_ / 128, BT_ / 128);
        gemm_h<<<gq, 256>>>(xh, wqh, qh, BT_, D_, D_, 1);
        dim3 gkv((KVH_ * HD_) / 128, BT_ / 128);
        gemm_h<<<gkv, 256>>>(xh, wkh, kh, BT_, KVH_ * HD_, D_, 1);
        gemm_h<<<gkv, 256>>>(xh, wvh, vh, BT_, KVH_ * HD_, D_, 1);
    }

    // RoPE on half q/k
    {
        int totq = BT_ * H_ * (HD_ / 2);
        rope_h_kernel<<<(totq + 255) / 256, 256>>>((__half2*)qh, fc, fs, H_, totq);
        int totk = BT_ * KVH_ * (HD_ / 2);
        rope_h_kernel<<<(totk + 255) / 256, 256>>>((__half2*)kh, fc, fs, KVH_, totk);
    }

    // Flash attention (fp16 mma)
    {
        dim3 g(T_ / 128, B_ * H_);
        flash_h<<<g, 256, FL_BYTES>>>(qh, kh, vh, ctxh);
    }

    // Output projection (fp16 in, fp32 out)
    {
        dim3 go(D_ / 128, BT_ / 128);
        gemm_h<<<go, 256>>>(ctxh, woh, out, BT_, D_, D_, 0);
    }
}